// round 5
// baseline (speedup 1.0000x reference)
#include <cuda_runtime.h>

#define NT 4000
#define NS 16
#define NR 512
#define NCOL (NS * NR)       // 8192 columns
#define NCOL4 (NCOL / 4)     // 2048 float4 columns
#define CHUNK 200
#define NCHUNK (NT / CHUNK)  // 20
#define GRIDX (NCOL4 / 256)  // 8
#define TOTAL_CTAS (GRIDX * NCHUNK * 2)  // 320

// Static device scratch (zero-initialized at module load; no allocation).
// g_key[inp][col] = (bits(v^2max) << 32) | (NT - argmax_t). atomicMax over
// these keys == argmax with first-occurrence tie-break (v^2 >= 0 so float
// bits are monotonic; equal bits -> larger NT-t -> smaller t wins).
__device__ unsigned long long g_key[2][NCOL];
__device__ unsigned           g_done = 0;   // re-armed by the tail CTA each run

__global__ void __launch_bounds__(256) tt_fused(const float* __restrict__ x,
                                                const float* __restrict__ y,
                                                float* __restrict__ out) {
    const int c4    = blockIdx.x * blockDim.x + threadIdx.x;  // 0..2047
    const int chunk = blockIdx.y;
    const int inp   = blockIdx.z;
    const float* v  = inp ? y : x;

    const float4* p = reinterpret_cast<const float4*>(v)
                      + (size_t)chunk * CHUNK * NCOL4 + c4;

    float m0 = -1.0f, m1 = -1.0f, m2 = -1.0f, m3 = -1.0f;
    int   i0 = 0, i1 = 0, i2 = 0, i3 = 0;
    const int tbase = chunk * CHUNK;

    // 8 independent LDG.128 in flight per thread; fully coalesced rows.
    for (int t = 0; t < CHUNK; t += 8) {
        float4 a[8];
#pragma unroll
        for (int u = 0; u < 8; u++)
            a[u] = p[(size_t)(t + u) * NCOL4];
#pragma unroll
        for (int u = 0; u < 8; u++) {
            const int ti = tbase + t + u;
            const float e0 = a[u].x * a[u].x;
            const float e1 = a[u].y * a[u].y;
            const float e2 = a[u].z * a[u].z;
            const float e3 = a[u].w * a[u].w;
            if (e0 > m0) { m0 = e0; i0 = ti; }   // strict > : first occurrence wins
            if (e1 > m1) { m1 = e1; i1 = ti; }
            if (e2 > m2) { m2 = e2; i2 = ti; }
            if (e3 > m3) { m3 = e3; i3 = ti; }
        }
    }

    // Publish this chunk's candidate via packed-key atomic max (RED, no return).
    const int col = c4 * 4;
    unsigned long long* kp = &g_key[inp][col];
    const unsigned long long k0 =
        ((unsigned long long)__float_as_uint(m0) << 32) | (unsigned)(NT - i0);
    const unsigned long long k1 =
        ((unsigned long long)__float_as_uint(m1) << 32) | (unsigned)(NT - i1);
    const unsigned long long k2 =
        ((unsigned long long)__float_as_uint(m2) << 32) | (unsigned)(NT - i2);
    const unsigned long long k3 =
        ((unsigned long long)__float_as_uint(m3) << 32) | (unsigned)(NT - i3);
    atomicMax(kp + 0, k0);
    atomicMax(kp + 1, k1);
    atomicMax(kp + 2, k2);
    atomicMax(kp + 3, k3);

    // ── Tail: last-arriving CTA computes the MSE and re-arms scratch. ──
    __shared__ bool   is_last;
    __shared__ double sh[256];

    __threadfence();                            // atomics visible before ticket
    if (threadIdx.x == 0) {
        unsigned t = atomicAdd(&g_done, 1u);
        is_last = (t == TOTAL_CTAS - 1);
    }
    __syncthreads();
    if (!is_last) return;

    const unsigned long long* kx = &g_key[0][0];
    const unsigned long long* ky = &g_key[1][0];
    double acc = 0.0;
#pragma unroll
    for (int c = threadIdx.x; c < NCOL; c += 256) {
        const unsigned long long ax = __ldcg(kx + c);   // L2-coherent loads
        const unsigned long long ay = __ldcg(ky + c);
        const int tx_ = NT - (int)(unsigned)(ax & 0xFFFFFFFFull);
        const int ty_ = NT - (int)(unsigned)(ay & 0xFFFFFFFFull);
        const float d = (float)tx_ - (float)ty_;        // exact: |d| < 4000
        acc += (double)d * (double)d;                   // exact
    }

    sh[threadIdx.x] = acc;
    __syncthreads();
#pragma unroll
    for (int s = 128; s > 0; s >>= 1) {
        if (threadIdx.x < s) sh[threadIdx.x] += sh[threadIdx.x + s];
        __syncthreads();
    }
    if (threadIdx.x == 0)
        out[0] = (float)(sh[0] * (1.0 / (double)NCOL));

    // Re-arm scratch for the next graph replay (deterministic).
    unsigned long long* kflat = &g_key[0][0];
    for (int c = threadIdx.x; c < 2 * NCOL; c += 256)
        kflat[c] = 0ull;
    if (threadIdx.x == 0) g_done = 0;
}

extern "C" void kernel_launch(void* const* d_in, const int* in_sizes, int n_in,
                              void* d_out, int out_size) {
    const float* x = (const float*)d_in[0];
    const float* y = (const float*)d_in[1];
    float* out = (float*)d_out;

    dim3 grid(GRIDX, NCHUNK, 2);
    tt_fused<<<grid, 256>>>(x, y, out);
}